// round 16
// baseline (speedup 1.0000x reference)
#include <cuda_runtime.h>
#include <math.h>

#define BB 8
#define CC 256
#define TT 16
#define HWN 1024
#define CR 16
#define G 1024   // persistent grid; 7 CTAs/SM * 148 = 1036 >= 1024 (co-resident)

// ---------------- scratch (device globals; no allocation) -------------------
__device__ float g_sp[BB * CC * HWN];   // spatial pooled mean  [b, c, hw] (8MB)
__device__ float g_tp[BB * CC * TT];    // temporal pooled mean [b, c, t]
__device__ float g_cp[BB * CC];         // channel pooled mean  [b, c]
__device__ float g_comb[BB * CC * TT];  // temporal_att * channel_att
__device__ float g_att[BB * CC * HWN];  // spatial attention (8MB)
__device__ unsigned g_barcnt;           // barrier arrival counter
__device__ unsigned g_bargen;           // barrier generation

__device__ __forceinline__ float sigmoidf(float a) {
    return 1.0f / (1.0f + __expf(-a));
}

// all-CTA barrier; safe because all G CTAs are co-resident.
__device__ __forceinline__ void grid_barrier() {
    __syncthreads();
    if (threadIdx.x == 0) {
        volatile unsigned* genp = &g_bargen;
        const unsigned gen = *genp;          // read BEFORE arrival
        __threadfence();                     // publish this CTA's writes
        const unsigned a = atomicAdd(&g_barcnt, 1u);
        if (a == (unsigned)(G - 1)) {
            atomicExch(&g_barcnt, 0u);
            __threadfence();
            atomicAdd(&g_bargen, 1u);        // release
        } else {
            while (*genp == gen) { __nanosleep(64); }
        }
        __threadfence();                     // acquire
    }
    __syncthreads();
}

// ---------------- fused persistent kernel ------------------------------------
__global__ void __launch_bounds__(256, 7) fused_kernel(
        const float* __restrict__ x,
        const float* __restrict__ ws1, const float* __restrict__ bs1,
        const float* __restrict__ ws2, const float* __restrict__ bs2,
        const float* __restrict__ wt1, const float* __restrict__ bt1,
        const float* __restrict__ wt2, const float* __restrict__ bt2,
        const float* __restrict__ wc1, const float* __restrict__ bc1,
        const float* __restrict__ wc2, const float* __restrict__ bc2,
        float* __restrict__ out) {
    __shared__ float sm[4096];   // 16 KB, reused per phase
    const int tid = threadIdx.x;
    const int bid = blockIdx.x;

    // ===== Phase A: pooling, contiguous reads; 2048 (b,c) jobs, 2/CTA ========
    {
        float* wsum = sm;   // [8 warps][16 t]
        const int lane = tid & 31;
        const int wid  = tid >> 5;

        for (int bc = bid; bc < BB * CC; bc += G) {
            const float4* xb = (const float4*)(x + (size_t)bc * (TT * HWN));
            float4 sp = make_float4(0.f, 0.f, 0.f, 0.f);

#pragma unroll
            for (int half = 0; half < 2; half++) {
                float tpar[8];
#pragma unroll
                for (int th = 0; th < 8; th++) {
                    const int t = half * 8 + th;
                    float4 v = xb[t * (HWN / 4) + tid];
                    sp.x += v.x; sp.y += v.y; sp.z += v.z; sp.w += v.w;
                    tpar[th] = (v.x + v.y) + (v.z + v.w);
                }
#pragma unroll
                for (int th = 0; th < 8; th++) {
                    float s = tpar[th];
#pragma unroll
                    for (int off = 16; off > 0; off >>= 1)
                        s += __shfl_down_sync(0xffffffffu, s, off);
                    if (lane == 0) wsum[wid * 16 + half * 8 + th] = s;
                }
            }

            float4 spo;
            spo.x = sp.x * (1.f / TT); spo.y = sp.y * (1.f / TT);
            spo.z = sp.z * (1.f / TT); spo.w = sp.w * (1.f / TT);
            ((float4*)(g_sp + (size_t)bc * HWN))[tid] = spo;

            __syncthreads();
            if (tid < TT) {
                float s = 0.f;
#pragma unroll
                for (int w = 0; w < 8; w++) s += wsum[w * 16 + tid];
                g_tp[bc * TT + tid] = s * (1.f / HWN);
                wsum[tid] = s;   // reuse row 0 (distinct columns)
            }
            __syncthreads();
            if (tid == 0) {
                float tot = 0.f;
#pragma unroll
                for (int t = 0; t < TT; t++) tot += wsum[t];
                g_cp[bc] = tot * (1.f / (TT * HWN));
            }
            __syncthreads();
        }
    }
    grid_barrier();

    // ===== Phase B: spatial att (all CTAs) + small SE (bid<128) ==============
    {
        // ---- att job = (b, 8-hw window), from L2-resident g_sp ----
        const int b   = bid >> 7;
        const int hw0 = (bid & 127) * 8;
        float* sp_s = sm;                 // [c][hw]  2048
        float* part = sm + 2048;          // [q][r][hw] 256
        float* hidf = sm + 2048 + 256;    // [r][hw] 128

        // stage sp slice: thread = channel, 2 float4 (32B at 4KB stride, L2)
        {
            const float4* src = (const float4*)(g_sp + ((size_t)(b * CC + tid)) * HWN + hw0);
            float4 a0 = __ldcg(src);
            float4 a1 = __ldcg(src + 1);
            ((float4*)(sp_s + tid * 8))[0] = a0;
            ((float4*)(sp_s + tid * 8))[1] = a1;
        }
        __syncthreads();

        // partial hidden: thread = (q, r, hw); 128 channels each, 1 accumulator
        {
            const int hw = tid & 7;
            const int r  = (tid >> 3) & 15;
            const int q  = tid >> 7;
            float acc = 0.f;
            const float4* w1p = (const float4*)(ws1 + r * CC + q * 128);
#pragma unroll 8
            for (int i = 0; i < 32; i++) {
                const float4 w = __ldg(w1p + i);
                const int c = q * 128 + i * 4;
                acc = fmaf(w.x, sp_s[(c + 0) * 8 + hw], acc);
                acc = fmaf(w.y, sp_s[(c + 1) * 8 + hw], acc);
                acc = fmaf(w.z, sp_s[(c + 2) * 8 + hw], acc);
                acc = fmaf(w.w, sp_s[(c + 3) * 8 + hw], acc);
            }
            part[tid] = acc;
        }
        __syncthreads();
        if (tid < 128) {
            const float h = __ldg(&bs1[tid >> 3]) + part[tid] + part[128 + tid];
            hidf[tid] = fmaxf(h, 0.f);
        }
        __syncthreads();

        // att: thread = (c8, hwl), 8 channels
        {
            const int c8  = tid >> 3;
            const int hwl = tid & 7;
            float* attb = g_att + (size_t)(b * CC) * HWN + hw0 + hwl;
#pragma unroll
            for (int i = 0; i < 8; i++) {
                const int c = c8 * 8 + i;
                const float4* wr = (const float4*)(ws2 + c * CR);
                float a = __ldg(&bs2[c]);
                {
                    const float4 w0 = __ldg(wr + 0);
                    a = fmaf(w0.x, hidf[0 * 8 + hwl], a);
                    a = fmaf(w0.y, hidf[1 * 8 + hwl], a);
                    a = fmaf(w0.z, hidf[2 * 8 + hwl], a);
                    a = fmaf(w0.w, hidf[3 * 8 + hwl], a);
                }
                {
                    const float4 w1 = __ldg(wr + 1);
                    a = fmaf(w1.x, hidf[4 * 8 + hwl], a);
                    a = fmaf(w1.y, hidf[5 * 8 + hwl], a);
                    a = fmaf(w1.z, hidf[6 * 8 + hwl], a);
                    a = fmaf(w1.w, hidf[7 * 8 + hwl], a);
                }
                {
                    const float4 w2 = __ldg(wr + 2);
                    a = fmaf(w2.x, hidf[8 * 8 + hwl],  a);
                    a = fmaf(w2.y, hidf[9 * 8 + hwl],  a);
                    a = fmaf(w2.z, hidf[10 * 8 + hwl], a);
                    a = fmaf(w2.w, hidf[11 * 8 + hwl], a);
                }
                {
                    const float4 w3 = __ldg(wr + 3);
                    a = fmaf(w3.x, hidf[12 * 8 + hwl], a);
                    a = fmaf(w3.y, hidf[13 * 8 + hwl], a);
                    a = fmaf(w3.z, hidf[14 * 8 + hwl], a);
                    a = fmaf(w3.w, hidf[15 * 8 + hwl], a);
                }
                attb[(size_t)c * HWN] = sigmoidf(a);
            }
        }
    }

    if (bid < 128) {
        // ---- temporal + channel SE -> g_comb ----
        __syncthreads();            // att done with sm
        const int b = bid >> 4;
        const int t = bid & 15;
        float* pt   = sm;           // [256]
        float* pc   = sm + 256;     // [256]
        float* hids = sm + 512;     // [32]

        pt[tid] = __ldcg(&g_tp[(b * CC + tid) * TT + t]);
        pc[tid] = __ldcg(&g_cp[b * CC + tid]);
        __syncthreads();

        if (tid < CR) {
            float s = bt1[tid];
            for (int c = 0; c < CC; c++) s = fmaf(wt1[tid * CC + c], pt[c], s);
            hids[tid] = fmaxf(s, 0.f);
        } else if (tid < 2 * CR) {
            const int r = tid - CR;
            float s = bc1[r];
            for (int c = 0; c < CC; c++) s = fmaf(wc1[r * CC + c], pc[c], s);
            hids[tid] = fmaxf(s, 0.f);
        }
        __syncthreads();

        float at = bt2[tid];
        float ac = bc2[tid];
#pragma unroll
        for (int r = 0; r < CR; r++) {
            at = fmaf(wt2[tid * CR + r], hids[r],      at);
            ac = fmaf(wc2[tid * CR + r], hids[CR + r], ac);
        }
        g_comb[(b * CC + tid) * TT + t] = sigmoidf(at) * sigmoidf(ac);
    }
    grid_barrier();

    // ===== Phase C: streaming apply (2048 jobs, 2 per CTA) ===================
    {
        float* smc = sm;   // [16]
        for (int j = bid; j < 2048; j += G) {
            if (tid < TT) smc[tid] = __ldcg(&g_comb[j * TT + tid]);
            __syncthreads();

            const float4 a = __ldcg(((const float4*)(g_att + (size_t)j * HWN)) + tid);
            const float4* xp = (const float4*)(x + (size_t)j * (TT * HWN));
            float4* op       = (float4*)(out + (size_t)j * (TT * HWN));
#pragma unroll
            for (int t = 0; t < TT; t++) {
                const float s = smc[t];
                float4 v = xp[t * (HWN / 4) + tid];
                v.x = v.x * a.x * s;
                v.y = v.y * a.y * s;
                v.z = v.z * a.z * s;
                v.w = v.w * a.w * s;
                op[t * (HWN / 4) + tid] = v;
            }
            __syncthreads();
        }
    }
}

// ---------------- launch -----------------------------------------------------
extern "C" void kernel_launch(void* const* d_in, const int* in_sizes, int n_in,
                              void* d_out, int out_size) {
    const float* x   = (const float*)d_in[0];
    const float* ws1 = (const float*)d_in[1];
    const float* bs1 = (const float*)d_in[2];
    const float* ws2 = (const float*)d_in[3];
    const float* bs2 = (const float*)d_in[4];
    const float* wt1 = (const float*)d_in[5];
    const float* bt1 = (const float*)d_in[6];
    const float* wt2 = (const float*)d_in[7];
    const float* bt2 = (const float*)d_in[8];
    const float* wc1 = (const float*)d_in[9];
    const float* bc1 = (const float*)d_in[10];
    const float* wc2 = (const float*)d_in[11];
    const float* bc2 = (const float*)d_in[12];
    float* out = (float*)d_out;

    fused_kernel<<<G, 256>>>(x, ws1, bs1, ws2, bs2,
                             wt1, bt1, wt2, bt2,
                             wc1, bc1, wc2, bc2, out);
}

// round 17
// speedup vs baseline: 1.4062x; 1.4062x over previous
#include <cuda_runtime.h>
#include <math.h>

#define BB 8
#define CC 256
#define TT 16
#define HWN 1024
#define CR 16

// ---------------- scratch (device globals; no allocation) -------------------
__device__ float g_sp[BB * CC * HWN];   // spatial pooled mean  [b, c, hw] (8MB)
__device__ float g_tp[BB * CC * TT];    // temporal pooled mean [b, c, t]
__device__ float g_cp[BB * CC];         // channel pooled mean  [b, c]
__device__ float g_hid[BB * CR * HWN];  // post-ReLU spatial hidden (512KB)
__device__ float g_comb[BB * CC * TT];  // temporal_att * channel_att

__device__ __forceinline__ float sigmoidf(float a) {
    return 1.0f / (1.0f + __expf(-a));
}

// ---------------- K1: pooling (R1 verbatim; measured 27.5us) -----------------
__global__ void __launch_bounds__(256) pool_kernel(const float* __restrict__ x) {
    const int bc  = blockIdx.x;
    const int tid = threadIdx.x;
    const float4* xb = (const float4*)(x + (size_t)bc * (TT * HWN));

    float4 sp = make_float4(0.f, 0.f, 0.f, 0.f);
    float tpar[TT];

#pragma unroll
    for (int t = 0; t < TT; t++) {
        float4 v = xb[t * (HWN / 4) + tid];
        sp.x += v.x; sp.y += v.y; sp.z += v.z; sp.w += v.w;
        tpar[t] = (v.x + v.y) + (v.z + v.w);
    }

    float4 spo;
    spo.x = sp.x * (1.f / TT); spo.y = sp.y * (1.f / TT);
    spo.z = sp.z * (1.f / TT); spo.w = sp.w * (1.f / TT);
    ((float4*)(g_sp + (size_t)bc * HWN))[tid] = spo;

    __shared__ float wsum[8][TT];
    const int lane = tid & 31;
    const int wid  = tid >> 5;
#pragma unroll
    for (int t = 0; t < TT; t++) {
        float s = tpar[t];
#pragma unroll
        for (int off = 16; off > 0; off >>= 1)
            s += __shfl_down_sync(0xffffffffu, s, off);
        if (lane == 0) wsum[wid][t] = s;
    }
    __syncthreads();
    if (tid < TT) {
        float s = 0.f;
#pragma unroll
        for (int w = 0; w < 8; w++) s += wsum[w][tid];
        g_tp[bc * TT + tid] = s * (1.f / HWN);
        wsum[0][tid] = s;
    }
    __syncthreads();
    if (tid == 0) {
        float tot = 0.f;
#pragma unroll
        for (int t = 0; t < TT; t++) tot += wsum[0][t];
        g_cp[bc] = tot * (1.f / (TT * HWN));
    }
}

// ---------------- K2: hidmid — spatial hidden (bid<256) + small SE -----------
// grid = 384, 256 threads, 32KB dyn smem.
// hid block = (b, 32-hw window); warp-per-channel-row coalesced 128B loads.
#define HM_SMEM_FLOATS (CC * 32)

__global__ void __launch_bounds__(256) hidmid_kernel(
        const float* __restrict__ ws1, const float* __restrict__ bs1,
        const float* __restrict__ wt1, const float* __restrict__ bt1,
        const float* __restrict__ wt2, const float* __restrict__ bt2,
        const float* __restrict__ wc1, const float* __restrict__ bc1,
        const float* __restrict__ wc2, const float* __restrict__ bc2) {
    extern __shared__ float sm[];
    const int tid = threadIdx.x;

    if (blockIdx.x < 256) {
        // ---- spatial first layer: g_sp -> g_hid ----
        const int b    = blockIdx.x >> 5;
        const int hw0  = (blockIdx.x & 31) * 32;
        const int w    = tid >> 5;
        const int lane = tid & 31;

        // stage sp[c][hw] : warp w loads channels w*32..w*32+31, one 128B line each
#pragma unroll 8
        for (int i = 0; i < 32; i++) {
            const int c = w * 32 + i;
            sm[c * 32 + lane] = g_sp[(size_t)(b * CC + c) * HWN + hw0 + lane];
        }
        __syncthreads();

        // hid: 512 outputs (16 r x 32 hw); thread handles (r, hw) and (r+8, hw)
        const int r0 = tid >> 5;        // 0..7
        const int r1 = r0 + 8;          // 8..15
        const int hw = tid & 31;
        float a0 = __ldg(&bs1[r0]);
        float a1 = __ldg(&bs1[r1]);
#pragma unroll 8
        for (int c = 0; c < CC; c++) {
            const float v = sm[c * 32 + hw];
            a0 = fmaf(__ldg(&ws1[r0 * CC + c]), v, a0);
            a1 = fmaf(__ldg(&ws1[r1 * CC + c]), v, a1);
        }
        g_hid[(size_t)(b * CR + r0) * HWN + hw0 + hw] = fmaxf(a0, 0.f);
        g_hid[(size_t)(b * CR + r1) * HWN + hw0 + hw] = fmaxf(a1, 0.f);
    } else {
        // ---- temporal + channel SE -> g_comb (proven design) ----
        const int idx = blockIdx.x - 256;   // 0..127
        const int b   = idx >> 4;
        const int t   = idx & 15;

        float* pt   = sm;          // [256]
        float* pc   = sm + 256;    // [256]
        float* hids = sm + 512;    // [32]

        pt[tid] = g_tp[(b * CC + tid) * TT + t];
        pc[tid] = g_cp[b * CC + tid];
        __syncthreads();

        if (tid < CR) {
            float s = bt1[tid];
            for (int c = 0; c < CC; c++) s = fmaf(wt1[tid * CC + c], pt[c], s);
            hids[tid] = fmaxf(s, 0.f);
        } else if (tid < 2 * CR) {
            const int r = tid - CR;
            float s = bc1[r];
            for (int c = 0; c < CC; c++) s = fmaf(wc1[r * CC + c], pc[c], s);
            hids[tid] = fmaxf(s, 0.f);
        }
        __syncthreads();

        float at = bt2[tid];
        float ac = bc2[tid];
#pragma unroll
        for (int r = 0; r < CR; r++) {
            at = fmaf(wt2[tid * CR + r], hids[r],      at);
            ac = fmaf(wc2[tid * CR + r], hids[CR + r], ac);
        }
        g_comb[(b * CC + tid) * TT + t] = sigmoidf(at) * sigmoidf(ac);
    }
}

// ---------------- K3: apply, spatial att reconstructed from hid --------------
// (R5 verbatim; measured 43.9us @ 62.7% DRAM)
__global__ void __launch_bounds__(256) apply_kernel(const float* __restrict__ x,
                                                    const float* __restrict__ ws2,
                                                    const float* __restrict__ bs2,
                                                    float* __restrict__ out) {
    const int bc  = blockIdx.x;
    const int b   = bc >> 8;
    const int c   = bc & 255;
    const int tid = threadIdx.x;

    __shared__ float combs[TT];
    __shared__ float w2s[CR];
    if (tid < TT) combs[tid] = g_comb[bc * TT + tid];
    if (tid >= 32 && tid < 32 + CR) w2s[tid - 32] = ws2[c * CR + (tid - 32)];
    __syncthreads();

    const float b2 = bs2[c];
    float4 a = make_float4(b2, b2, b2, b2);
    const float4* hp = (const float4*)(g_hid + (size_t)b * CR * HWN);
#pragma unroll
    for (int r = 0; r < CR; r++) {
        const float4 h = hp[r * (HWN / 4) + tid];
        const float w = w2s[r];
        a.x = fmaf(w, h.x, a.x);
        a.y = fmaf(w, h.y, a.y);
        a.z = fmaf(w, h.z, a.z);
        a.w = fmaf(w, h.w, a.w);
    }
    a.x = sigmoidf(a.x); a.y = sigmoidf(a.y);
    a.z = sigmoidf(a.z); a.w = sigmoidf(a.w);

    const float4* xp = (const float4*)(x + (size_t)bc * (TT * HWN));
    float4* op       = (float4*)(out + (size_t)bc * (TT * HWN));
#pragma unroll
    for (int t = 0; t < TT; t++) {
        const float s = combs[t];
        float4 v = xp[t * (HWN / 4) + tid];
        v.x = v.x * a.x * s;
        v.y = v.y * a.y * s;
        v.z = v.z * a.z * s;
        v.w = v.w * a.w * s;
        op[t * (HWN / 4) + tid] = v;
    }
}

// ---------------- launch -----------------------------------------------------
extern "C" void kernel_launch(void* const* d_in, const int* in_sizes, int n_in,
                              void* d_out, int out_size) {
    const float* x   = (const float*)d_in[0];
    const float* ws1 = (const float*)d_in[1];
    const float* bs1 = (const float*)d_in[2];
    const float* ws2 = (const float*)d_in[3];
    const float* bs2 = (const float*)d_in[4];
    const float* wt1 = (const float*)d_in[5];
    const float* bt1 = (const float*)d_in[6];
    const float* wt2 = (const float*)d_in[7];
    const float* bt2 = (const float*)d_in[8];
    const float* wc1 = (const float*)d_in[9];
    const float* bc1 = (const float*)d_in[10];
    const float* wc2 = (const float*)d_in[11];
    const float* bc2 = (const float*)d_in[12];
    float* out = (float*)d_out;

    pool_kernel<<<BB * CC, 256>>>(x);
    hidmid_kernel<<<384, 256, HM_SMEM_FLOATS * sizeof(float)>>>(
        ws1, bs1, wt1, bt1, wt2, bt2, wc1, bc1, wc2, bc2);
    apply_kernel<<<BB * CC, 256>>>(x, ws2, bs2, out);
}